// round 13
// baseline (speedup 1.0000x reference)
#include <cuda_runtime.h>
#include <cuda_fp16.h>
#include <cstdint>

#define N_NODES 100000
#define N_EDGES 1600000
#define IN_C 128
#define OUT_C 128
#define CAP 128                     // bucket capacity per node (deg ~ Poisson(32))

// fused gemm+fill kernel geometry: GEMM M=64/block, warp tile m16 x n64
#define GEMM_M_BLK 64
#define GEMM_BLOCKS ((N_NODES + GEMM_M_BLK - 1) / GEMM_M_BLK)   // 1563
#define FILL_EPT 2
#define FILL_THREADS 256
#define FILL_BLOCKS (N_EDGES / (FILL_THREADS * FILL_EPT))       // 3125 exact
#define FUSED_BLOCKS (GEMM_BLOCKS + FILL_BLOCKS)                // 4688

#define WT_PAD 8
#define WT_LD (IN_C + WT_PAD)   // 136 halves row stride

// ---- scratch in __device__ globals (no cudaMalloc allowed) ----
__device__ __half g_xwh[(size_t)N_NODES * OUT_C]; // 25.6 MB, UNSCALED fp16 x@W
__device__ float  g_dinv[N_NODES];
__device__ int    g_cursor[N_NODES];              // zeroed; fill bumps -> deg
__device__ int    g_col[(size_t)N_NODES * CAP];   // 51.2 MB bucketed adjacency

__device__ __forceinline__ unsigned h2_to_u32(__half2 h) {
    return *reinterpret_cast<unsigned*>(&h);
}

// ------------------------------------------------------------------
__global__ void k_zero_cursor() {
    int i = blockIdx.x * blockDim.x + threadIdx.x;
    if (i < N_NODES) g_cursor[i] = 0;
}

// dinv from bucket counts (full degree even if adjacency were truncated)
__global__ void k_dinv() {
    int i = blockIdx.x * blockDim.x + threadIdx.x;
    if (i < N_NODES) g_dinv[i] = rsqrtf((float)g_cursor[i] + 1.0f);
}

// ------------------------------------------------------------------
// Fused GEMM (unscaled fp16 out) + one-pass bucketed fill.
// GEMM every 3rd block (1563), fill otherwise (3125).
__global__ __launch_bounds__(256, 4) void k_gemm_fill(const float* __restrict__ x,
                                                      const float* __restrict__ W,
                                                      const int* __restrict__ ei) {
    const int bid = blockIdx.x;
    const bool is_gemm = (bid % 3 == 0);

    if (!is_gemm) {
        // ---------------- fill role: one-pass bucket insert ----------------
        const int fill_id = bid - bid / 3 - 1;
        int e = (fill_id * FILL_THREADS + threadIdx.x) * FILL_EPT;
        if (e + 1 < N_EDGES) {
            int a0 = ei[e],     b0 = ei[N_EDGES + e];
            int a1 = ei[e + 1], b1 = ei[N_EDGES + e + 1];
            int p0 = atomicAdd(&g_cursor[a0], 1);
            int p1 = atomicAdd(&g_cursor[b0], 1);
            int p2 = atomicAdd(&g_cursor[a1], 1);
            int p3 = atomicAdd(&g_cursor[b1], 1);
            if (p0 < CAP) g_col[(size_t)a0 * CAP + p0] = b0;
            if (p1 < CAP) g_col[(size_t)b0 * CAP + p1] = a0;
            if (p2 < CAP) g_col[(size_t)a1 * CAP + p2] = b1;
            if (p3 < CAP) g_col[(size_t)b1 * CAP + p3] = a1;
        } else if (e < N_EDGES) {
            int a = ei[e];
            int b = ei[N_EDGES + e];
            int pa = atomicAdd(&g_cursor[a], 1);
            int pb = atomicAdd(&g_cursor[b], 1);
            if (pa < CAP) g_col[(size_t)a * CAP + pa] = b;
            if (pb < CAP) g_col[(size_t)b * CAP + pb] = a;
        }
        return;
    }

    // ---------------- GEMM role: M=64, 8 warps = 4 m-tiles x 2 n-halves ----------------
    __shared__ __half wt[OUT_C][WT_LD];   // W^T: wt[n][k]
    const int gemm_id = bid / 3;
    const int tid  = threadIdx.x;
    const int wid  = tid >> 5;            // 0..7
    const int lane = tid & 31;

    for (int i = tid; i < IN_C * OUT_C; i += 256) {
        int k = i >> 7;
        int n = i & 127;
        wt[n][k] = __float2half(W[(size_t)k * OUT_C + n]);
    }
    __syncthreads();

    const int m_tile  = wid >> 1;          // 0..3
    const int n_half  = (wid & 1) * 64;    // 0 or 64
    const int row_base = gemm_id * GEMM_M_BLK + m_tile * 16;
    const int qr = lane >> 2;
    const int qc = lane & 3;
    const int r0 = row_base + qr;
    const int r1 = r0 + 8;
    const int r0c = (r0 < N_NODES) ? r0 : (N_NODES - 1);
    const int r1c = (r1 < N_NODES) ? r1 : (N_NODES - 1);
    const float* xr0 = x + (size_t)r0c * IN_C;
    const float* xr1 = x + (size_t)r1c * IN_C;

    float acc[8][4];
    #pragma unroll
    for (int nt = 0; nt < 8; nt++)
        #pragma unroll
        for (int q = 0; q < 4; q++) acc[nt][q] = 0.0f;

    #pragma unroll
    for (int ks = 0; ks < IN_C / 16; ks++) {
        const int k0 = ks * 16 + qc * 2;
        float2 f;
        f = *(const float2*)(xr0 + k0);     unsigned a0 = h2_to_u32(__float22half2_rn(f));
        f = *(const float2*)(xr1 + k0);     unsigned a1 = h2_to_u32(__float22half2_rn(f));
        f = *(const float2*)(xr0 + k0 + 8); unsigned a2 = h2_to_u32(__float22half2_rn(f));
        f = *(const float2*)(xr1 + k0 + 8); unsigned a3 = h2_to_u32(__float22half2_rn(f));

        #pragma unroll
        for (int nt = 0; nt < 8; nt++) {
            const int n = n_half + nt * 8 + qr;
            unsigned b0 = *(const unsigned*)&wt[n][k0];
            unsigned b1 = *(const unsigned*)&wt[n][k0 + 8];
            asm volatile(
                "mma.sync.aligned.m16n8k16.row.col.f32.f16.f16.f32 "
                "{%0,%1,%2,%3}, {%4,%5,%6,%7}, {%8,%9}, {%0,%1,%2,%3};\n"
                : "+f"(acc[nt][0]), "+f"(acc[nt][1]), "+f"(acc[nt][2]), "+f"(acc[nt][3])
                : "r"(a0), "r"(a1), "r"(a2), "r"(a3), "r"(b0), "r"(b1));
        }
    }

    // epilogue: store unscaled fp16 pairs (single rounding happens here)
    #pragma unroll
    for (int nt = 0; nt < 8; nt++) {
        const int n = n_half + nt * 8 + qc * 2;
        if (r0 < N_NODES) {
            __half2 h = __floats2half2_rn(acc[nt][0], acc[nt][1]);
            *(__half2*)(g_xwh + (size_t)r0 * OUT_C + n) = h;
        }
        if (r1 < N_NODES) {
            __half2 h = __floats2half2_rn(acc[nt][2], acc[nt][3]);
            *(__half2*)(g_xwh + (size_t)r1 * OUT_C + n) = h;
        }
    }
}

// ------------------------------------------------------------------
// gather SpMM + self-loop + bias. One warp per destination node.
// y[n] = dinv[n] * ( sum_c dinv[c]*xw[c] + dinv[n]*xw[n] ) + b
__global__ void k_gather(const float* __restrict__ b, float* __restrict__ y) {
    const int node = (blockIdx.x * blockDim.x + threadIdx.x) >> 5;
    const int lane = threadIdx.x & 31;
    if (node >= N_NODES) return;

    int len = g_cursor[node];
    if (len > CAP) len = CAP;
    const int beg = node * CAP;
    const int end = beg + len;
    const float dn = g_dinv[node];

    float ax = 0.f, ay = 0.f, az = 0.f, aw = 0.f;

    int j = beg;
    for (; j + 8 <= end; j += 8) {
        int c0 = g_col[j + 0], c1 = g_col[j + 1], c2 = g_col[j + 2], c3 = g_col[j + 3];
        int c4 = g_col[j + 4], c5 = g_col[j + 5], c6 = g_col[j + 6], c7 = g_col[j + 7];
        float w0 = g_dinv[c0], w1 = g_dinv[c1], w2 = g_dinv[c2], w3 = g_dinv[c3];
        float w4 = g_dinv[c4], w5 = g_dinv[c5], w6 = g_dinv[c6], w7 = g_dinv[c7];
        uint2 u0 = ((const uint2*)(g_xwh + (size_t)c0 * OUT_C))[lane];
        uint2 u1 = ((const uint2*)(g_xwh + (size_t)c1 * OUT_C))[lane];
        uint2 u2 = ((const uint2*)(g_xwh + (size_t)c2 * OUT_C))[lane];
        uint2 u3 = ((const uint2*)(g_xwh + (size_t)c3 * OUT_C))[lane];
        uint2 u4 = ((const uint2*)(g_xwh + (size_t)c4 * OUT_C))[lane];
        uint2 u5 = ((const uint2*)(g_xwh + (size_t)c5 * OUT_C))[lane];
        uint2 u6 = ((const uint2*)(g_xwh + (size_t)c6 * OUT_C))[lane];
        uint2 u7 = ((const uint2*)(g_xwh + (size_t)c7 * OUT_C))[lane];
        #define ACCUMW(u, w) { \
            float2 f0 = __half22float2(*(const __half2*)&(u).x); \
            float2 f1 = __half22float2(*(const __half2*)&(u).y); \
            ax = fmaf((w), f0.x, ax); ay = fmaf((w), f0.y, ay); \
            az = fmaf((w), f1.x, az); aw = fmaf((w), f1.y, aw); }
        ACCUMW(u0, w0) ACCUMW(u1, w1) ACCUMW(u2, w2) ACCUMW(u3, w3)
        ACCUMW(u4, w4) ACCUMW(u5, w5) ACCUMW(u6, w6) ACCUMW(u7, w7)
    }
    for (; j < end; j++) {
        const int c = g_col[j];
        const float w = g_dinv[c];
        uint2 u = ((const uint2*)(g_xwh + (size_t)c * OUT_C))[lane];
        ACCUMW(u, w)
    }
    // self-loop: + dn * xw[node]  (then outer dn gives dn^2)
    {
        uint2 u = ((const uint2*)(g_xwh + (size_t)node * OUT_C))[lane];
        ACCUMW(u, dn)
    }
    #undef ACCUMW

    const float4 bv = ((const float4*)b)[lane];
    float4 o;
    o.x = dn * ax + bv.x;
    o.y = dn * ay + bv.y;
    o.z = dn * az + bv.z;
    o.w = dn * aw + bv.w;
    ((float4*)(y + (size_t)node * OUT_C))[lane] = o;
}

// ------------------------------------------------------------------
extern "C" void kernel_launch(void* const* d_in, const int* in_sizes, int n_in,
                              void* d_out, int out_size) {
    const float* x  = (const float*)d_in[0];
    const float* W  = (const float*)d_in[1];
    const float* b  = (const float*)d_in[2];
    const int*   ei = (const int*)d_in[3];
    float* y = (float*)d_out;

    // zero bucket cursors
    k_zero_cursor<<<(N_NODES + 255) / 256, 256>>>();

    // fused tensor-core GEMM (unscaled fp16) + one-pass bucketed fill
    k_gemm_fill<<<FUSED_BLOCKS, 256>>>(x, W, ei);

    // dinv from final counts
    k_dinv<<<(N_NODES + 255) / 256, 256>>>();

    // fused gather + self-loop + bias: one warp per node
    const int gather_blocks = (N_NODES * 32 + 255) / 256;
    k_gather<<<gather_blocks, 256>>>(b, y);
}

// round 14
// speedup vs baseline: 1.0831x; 1.0831x over previous
#include <cuda_runtime.h>
#include <cuda_fp16.h>
#include <cstdint>

#define N_NODES 100000
#define N_EDGES 1600000
#define IN_C 128
#define OUT_C 128
#define CAP 128                     // bucket capacity per node (deg ~ Poisson(32))

// fused gemm+fill kernel geometry: GEMM M=64/block, warp tile m16 x n64
#define GEMM_M_BLK 64
#define GEMM_BLOCKS ((N_NODES + GEMM_M_BLK - 1) / GEMM_M_BLK)   // 1563
#define FILL_EPT 2
#define FILL_THREADS 256
#define FILL_BLOCKS (N_EDGES / (FILL_THREADS * FILL_EPT))       // 3125 exact
#define FUSED_BLOCKS (GEMM_BLOCKS + FILL_BLOCKS)                // 4688

#define WT_PAD 8
#define WT_LD (IN_C + WT_PAD)   // 136 halves row stride

// ---- scratch in __device__ globals (no cudaMalloc allowed) ----
__device__ __half g_xwh[(size_t)N_NODES * OUT_C]; // 25.6 MB; unscaled, then scaled in-place
__device__ float  g_dinv[N_NODES];
__device__ int    g_cursor[N_NODES];              // zeroed; fill bumps -> deg
__device__ int    g_col[(size_t)N_NODES * CAP];   // 51.2 MB bucketed adjacency

__device__ __forceinline__ unsigned h2_to_u32(__half2 h) {
    return *reinterpret_cast<unsigned*>(&h);
}

// ------------------------------------------------------------------
__global__ void k_zero_cursor() {
    int i = blockIdx.x * blockDim.x + threadIdx.x;
    if (i < N_NODES) g_cursor[i] = 0;
}

// ------------------------------------------------------------------
// Fused GEMM (unscaled fp16 out) + one-pass bucketed fill.
// GEMM every 3rd block (1563), fill otherwise (3125).
__global__ __launch_bounds__(256, 4) void k_gemm_fill(const float* __restrict__ x,
                                                      const float* __restrict__ W,
                                                      const int* __restrict__ ei) {
    const int bid = blockIdx.x;
    const bool is_gemm = (bid % 3 == 0);

    if (!is_gemm) {
        // ---------------- fill role: one-pass bucket insert ----------------
        const int fill_id = bid - bid / 3 - 1;
        int e = (fill_id * FILL_THREADS + threadIdx.x) * FILL_EPT;
        if (e + 1 < N_EDGES) {
            int a0 = ei[e],     b0 = ei[N_EDGES + e];
            int a1 = ei[e + 1], b1 = ei[N_EDGES + e + 1];
            int p0 = atomicAdd(&g_cursor[a0], 1);
            int p1 = atomicAdd(&g_cursor[b0], 1);
            int p2 = atomicAdd(&g_cursor[a1], 1);
            int p3 = atomicAdd(&g_cursor[b1], 1);
            if (p0 < CAP) g_col[(size_t)a0 * CAP + p0] = b0;
            if (p1 < CAP) g_col[(size_t)b0 * CAP + p1] = a0;
            if (p2 < CAP) g_col[(size_t)a1 * CAP + p2] = b1;
            if (p3 < CAP) g_col[(size_t)b1 * CAP + p3] = a1;
        } else if (e < N_EDGES) {
            int a = ei[e];
            int b = ei[N_EDGES + e];
            int pa = atomicAdd(&g_cursor[a], 1);
            int pb = atomicAdd(&g_cursor[b], 1);
            if (pa < CAP) g_col[(size_t)a * CAP + pa] = b;
            if (pb < CAP) g_col[(size_t)b * CAP + pb] = a;
        }
        return;
    }

    // ---------------- GEMM role: M=64, 8 warps = 4 m-tiles x 2 n-halves ----------------
    __shared__ __half wt[OUT_C][WT_LD];   // W^T: wt[n][k]
    const int gemm_id = bid / 3;
    const int tid  = threadIdx.x;
    const int wid  = tid >> 5;            // 0..7
    const int lane = tid & 31;

    for (int i = tid; i < IN_C * OUT_C; i += 256) {
        int k = i >> 7;
        int n = i & 127;
        wt[n][k] = __float2half(W[(size_t)k * OUT_C + n]);
    }
    __syncthreads();

    const int m_tile  = wid >> 1;          // 0..3
    const int n_half  = (wid & 1) * 64;    // 0 or 64
    const int row_base = gemm_id * GEMM_M_BLK + m_tile * 16;
    const int qr = lane >> 2;
    const int qc = lane & 3;
    const int r0 = row_base + qr;
    const int r1 = r0 + 8;
    const int r0c = (r0 < N_NODES) ? r0 : (N_NODES - 1);
    const int r1c = (r1 < N_NODES) ? r1 : (N_NODES - 1);
    const float* xr0 = x + (size_t)r0c * IN_C;
    const float* xr1 = x + (size_t)r1c * IN_C;

    float acc[8][4];
    #pragma unroll
    for (int nt = 0; nt < 8; nt++)
        #pragma unroll
        for (int q = 0; q < 4; q++) acc[nt][q] = 0.0f;

    #pragma unroll
    for (int ks = 0; ks < IN_C / 16; ks++) {
        const int k0 = ks * 16 + qc * 2;
        float2 f;
        f = *(const float2*)(xr0 + k0);     unsigned a0 = h2_to_u32(__float22half2_rn(f));
        f = *(const float2*)(xr1 + k0);     unsigned a1 = h2_to_u32(__float22half2_rn(f));
        f = *(const float2*)(xr0 + k0 + 8); unsigned a2 = h2_to_u32(__float22half2_rn(f));
        f = *(const float2*)(xr1 + k0 + 8); unsigned a3 = h2_to_u32(__float22half2_rn(f));

        #pragma unroll
        for (int nt = 0; nt < 8; nt++) {
            const int n = n_half + nt * 8 + qr;
            unsigned b0 = *(const unsigned*)&wt[n][k0];
            unsigned b1 = *(const unsigned*)&wt[n][k0 + 8];
            asm volatile(
                "mma.sync.aligned.m16n8k16.row.col.f32.f16.f16.f32 "
                "{%0,%1,%2,%3}, {%4,%5,%6,%7}, {%8,%9}, {%0,%1,%2,%3};\n"
                : "+f"(acc[nt][0]), "+f"(acc[nt][1]), "+f"(acc[nt][2]), "+f"(acc[nt][3])
                : "r"(a0), "r"(a1), "r"(a2), "r"(a3), "r"(b0), "r"(b1));
        }
    }

    // epilogue: store unscaled fp16 pairs
    #pragma unroll
    for (int nt = 0; nt < 8; nt++) {
        const int n = n_half + nt * 8 + qc * 2;
        if (r0 < N_NODES) {
            __half2 h = __floats2half2_rn(acc[nt][0], acc[nt][1]);
            *(__half2*)(g_xwh + (size_t)r0 * OUT_C + n) = h;
        }
        if (r1 < N_NODES) {
            __half2 h = __floats2half2_rn(acc[nt][2], acc[nt][3]);
            *(__half2*)(g_xwh + (size_t)r1 * OUT_C + n) = h;
        }
    }
}

// ------------------------------------------------------------------
// scale pass: dinv[n] = rsqrt(deg+1); xwh[n] *= dinv[n] in place (fp16 RMW).
// Warp per row, flat grid, fully coalesced uint2.
__global__ void k_scale() {
    const int gid  = blockIdx.x * blockDim.x + threadIdx.x;
    const int node = gid >> 5;
    const int lane = gid & 31;
    if (node >= N_NODES) return;

    const int d = g_cursor[node];
    const float dv = rsqrtf((float)d + 1.0f);
    if (lane == 0) g_dinv[node] = dv;

    uint2* p = (uint2*)(g_xwh + (size_t)node * OUT_C) + lane;
    uint2 u = *p;
    float2 f0 = __half22float2(*(const __half2*)&u.x);
    float2 f1 = __half22float2(*(const __half2*)&u.y);
    __half2 h0 = __floats2half2_rn(f0.x * dv, f0.y * dv);
    __half2 h1 = __floats2half2_rn(f1.x * dv, f1.y * dv);
    u.x = h2_to_u32(h0);
    u.y = h2_to_u32(h1);
    *p = u;
}

// ------------------------------------------------------------------
// gather SpMM + self-loop + bias. One warp per destination node.
__global__ void k_gather(const float* __restrict__ b, float* __restrict__ y) {
    const int node = (blockIdx.x * blockDim.x + threadIdx.x) >> 5;
    const int lane = threadIdx.x & 31;
    if (node >= N_NODES) return;

    int len = g_cursor[node];
    if (len > CAP) len = CAP;
    const int beg = node * CAP;
    const int end = beg + len;

    float ax = 0.f, ay = 0.f, az = 0.f, aw = 0.f;

    int j = beg;
    for (; j + 8 <= end; j += 8) {
        int c0 = g_col[j + 0], c1 = g_col[j + 1], c2 = g_col[j + 2], c3 = g_col[j + 3];
        int c4 = g_col[j + 4], c5 = g_col[j + 5], c6 = g_col[j + 6], c7 = g_col[j + 7];
        uint2 u0 = ((const uint2*)(g_xwh + (size_t)c0 * OUT_C))[lane];
        uint2 u1 = ((const uint2*)(g_xwh + (size_t)c1 * OUT_C))[lane];
        uint2 u2 = ((const uint2*)(g_xwh + (size_t)c2 * OUT_C))[lane];
        uint2 u3 = ((const uint2*)(g_xwh + (size_t)c3 * OUT_C))[lane];
        uint2 u4 = ((const uint2*)(g_xwh + (size_t)c4 * OUT_C))[lane];
        uint2 u5 = ((const uint2*)(g_xwh + (size_t)c5 * OUT_C))[lane];
        uint2 u6 = ((const uint2*)(g_xwh + (size_t)c6 * OUT_C))[lane];
        uint2 u7 = ((const uint2*)(g_xwh + (size_t)c7 * OUT_C))[lane];
        #define ACCUM(u) { \
            float2 f0 = __half22float2(*(const __half2*)&(u).x); \
            float2 f1 = __half22float2(*(const __half2*)&(u).y); \
            ax += f0.x; ay += f0.y; az += f1.x; aw += f1.y; }
        ACCUM(u0) ACCUM(u1) ACCUM(u2) ACCUM(u3)
        ACCUM(u4) ACCUM(u5) ACCUM(u6) ACCUM(u7)
    }
    for (; j < end; j++) {
        const int c = g_col[j];
        uint2 u = ((const uint2*)(g_xwh + (size_t)c * OUT_C))[lane];
        ACCUM(u)
    }
    {
        uint2 u = ((const uint2*)(g_xwh + (size_t)node * OUT_C))[lane];
        ACCUM(u)
    }
    #undef ACCUM

    const float dn = g_dinv[node];
    const float4 bv = ((const float4*)b)[lane];
    float4 o;
    o.x = dn * ax + bv.x;
    o.y = dn * ay + bv.y;
    o.z = dn * az + bv.z;
    o.w = dn * aw + bv.w;
    ((float4*)(y + (size_t)node * OUT_C))[lane] = o;
}

// ------------------------------------------------------------------
extern "C" void kernel_launch(void* const* d_in, const int* in_sizes, int n_in,
                              void* d_out, int out_size) {
    const float* x  = (const float*)d_in[0];
    const float* W  = (const float*)d_in[1];
    const float* b  = (const float*)d_in[2];
    const int*   ei = (const int*)d_in[3];
    float* y = (float*)d_out;

    // zero bucket cursors
    k_zero_cursor<<<(N_NODES + 255) / 256, 256>>>();

    // fused tensor-core GEMM (unscaled fp16) + one-pass bucketed fill
    k_gemm_fill<<<FUSED_BLOCKS, 256>>>(x, W, ei);

    // dinv + in-place fp16 prescale
    k_scale<<<(N_NODES * 32 + 255) / 256, 256>>>();

    // fused gather + self-loop + bias: one warp per node
    const int gather_blocks = (N_NODES * 32 + 255) / 256;
    k_gather<<<gather_blocks, 256>>>(b, y);
}